// round 10
// baseline (speedup 1.0000x reference)
#include <cuda_runtime.h>
#include <mma.h>
#include <stdint.h>

using namespace nvcuda;

#define NN   100000
#define INC  1024
#define HIDD 128
#define NE   1600000
#define NB   98          // ceil(NN/1024)
#define NNPAD 100096     // NN rounded up to 128 (GEMM overhang scratch)

// -------- scratch (device globals; no allocations allowed) --------
__device__ float g_hs[(size_t)NNPAD * HIDD];  // h = X @ W (unscaled), padded
__device__ float g_dinv[NN];
__device__ int   g_cnt[NN];
__device__ int   g_start[NN + 1];
__device__ int   g_cursor[NN];
__device__ int   g_srcbuf[NE];
__device__ int   g_bsum[NB];
__device__ int   g_boff[NB];

// ===================== graph-prep kernels =====================
__global__ void init_kernel() {
    int i = blockIdx.x * blockDim.x + threadIdx.x;
    if (i < NN) { g_cnt[i] = 0; g_cursor[i] = 0; }
}

__global__ void count_kernel(const int* __restrict__ ei) {
    int e = blockIdx.x * blockDim.x + threadIdx.x;
    if (e < NE) {
        int c = ei[NE + e];
        if ((unsigned)c < NN) atomicAdd(&g_cnt[c], 1);
    }
}

__global__ void dinv_kernel() {
    int i = blockIdx.x * blockDim.x + threadIdx.x;
    if (i < NN) g_dinv[i] = rsqrtf((float)g_cnt[i] + 1.0f);
}

// ---- decoupled 3-pass scan of g_cnt -> g_start (exclusive, len NN+1) ----
__global__ void blocksum_kernel() {
    __shared__ int ws[32];
    int i = blockIdx.x * 1024 + threadIdx.x;
    int lane = threadIdx.x & 31, wid = threadIdx.x >> 5;
    int v = (i < NN) ? g_cnt[i] : 0;
    #pragma unroll
    for (int off = 16; off > 0; off >>= 1)
        v += __shfl_down_sync(0xffffffff, v, off);
    if (lane == 0) ws[wid] = v;
    __syncthreads();
    if (wid == 0) {
        int s = ws[lane];
        #pragma unroll
        for (int off = 16; off > 0; off >>= 1)
            s += __shfl_down_sync(0xffffffff, s, off);
        if (lane == 0) g_bsum[blockIdx.x] = s;
    }
}

__global__ void bscan_kernel() {   // 1 block, 128 threads over NB=98
    __shared__ int wsum[4];
    int t = threadIdx.x, lane = t & 31, w = t >> 5;
    int v = (t < NB) ? g_bsum[t] : 0;
    int x = v;
    #pragma unroll
    for (int off = 1; off < 32; off <<= 1) {
        int y = __shfl_up_sync(0xffffffff, x, off);
        if (lane >= off) x += y;
    }
    if (lane == 31) wsum[w] = x;
    __syncthreads();
    if (t == 0) {
        int a = 0;
        #pragma unroll
        for (int j = 0; j < 4; j++) { int tmp = wsum[j]; wsum[j] = a; a += tmp; }
    }
    __syncthreads();
    if (t < NB) g_boff[t] = x - v + wsum[w];   // exclusive prefix
}

__global__ void bapply_kernel() {
    __shared__ int ws[32];
    int i = blockIdx.x * 1024 + threadIdx.x;
    int lane = threadIdx.x & 31, wid = threadIdx.x >> 5;
    int v = (i < NN) ? g_cnt[i] : 0;
    int x = v;
    #pragma unroll
    for (int off = 1; off < 32; off <<= 1) {
        int y = __shfl_up_sync(0xffffffff, x, off);
        if (lane >= off) x += y;
    }
    if (lane == 31) ws[wid] = x;
    __syncthreads();
    if (wid == 0) {
        int w = ws[lane];
        #pragma unroll
        for (int off = 1; off < 32; off <<= 1) {
            int y = __shfl_up_sync(0xffffffff, w, off);
            if (lane >= off) w += y;
        }
        ws[lane] = w;
    }
    __syncthreads();
    int incl = x + (wid > 0 ? ws[wid - 1] : 0) + g_boff[blockIdx.x];
    if (i < NN) g_start[i + 1] = incl;
    if (i == 0) g_start[0] = 0;
}

__global__ void fill_kernel(const int* __restrict__ ei) {
    int e = blockIdx.x * blockDim.x + threadIdx.x;
    if (e < NE) {
        int r = ei[e];
        int c = ei[NE + e];
        if ((unsigned)c < NN && (unsigned)r < NN) {
            int pos = atomicAdd(&g_cursor[c], 1);
            g_srcbuf[g_start[c] + pos] = r;
        }
    }
}

// ========= GEMM via WMMA tf32 + cp.async 3-stage single-barrier pipeline =========
// BM=128, BN=128, BK=32, 256 threads (8 warps: 2x4, each warp 64x32).
#define LDA 36     // 32 + 4 pad
#define LDB 136    // 128 + 8 pad
#define ASZ (128 * LDA)
#define BSZ (32 * LDB)
#define NC  (INC / 32)   // 32 K-chunks
#define STG 3
#define GEMM_SMEM (STG * (ASZ + BSZ) * 4)   // 107520 bytes

__device__ __forceinline__ uint32_t smem_u32(const void* p) {
    uint32_t a;
    asm("{ .reg .u64 t; cvta.to.shared.u64 t, %1; cvt.u32.u64 %0, t; }"
        : "=r"(a) : "l"(p));
    return a;
}
__device__ __forceinline__ void cp_async16(uint32_t dst, const void* src, int src_bytes) {
    asm volatile("cp.async.cg.shared.global [%0], [%1], 16, %2;"
                 :: "r"(dst), "l"(src), "r"(src_bytes));
}
#define CP_COMMIT() asm volatile("cp.async.commit_group;" ::: "memory")
#define CP_WAIT(N)  asm volatile("cp.async.wait_group %0;" :: "n"(N) : "memory")

__global__ __launch_bounds__(256)
void gemm_wmma_kernel(const float* __restrict__ X, const float* __restrict__ W) {
    extern __shared__ __align__(16) float smem[];
    float* sA[STG];
    float* sB[STG];
    #pragma unroll
    for (int s = 0; s < STG; s++) {
        sA[s] = smem + s * ASZ;
        sB[s] = smem + STG * ASZ + s * BSZ;
    }

    const int tid = threadIdx.x;
    const int wid = tid >> 5;
    const int wr = wid >> 2;          // 0..1  (64-row band)
    const int wc = wid & 3;           // 0..3  (32-col band)
    const int bm = blockIdx.x * 128;

    // per-thread staging coords (constant across chunks)
    const int arow = tid >> 3,  ac4 = (tid & 7) * 4;    // +32 rows per i
    const int brow = tid >> 5,  bc4 = (tid & 31) * 4;   // +8  rows per i
    uint32_t aAbase[STG], aBbase[STG];
    #pragma unroll
    for (int s = 0; s < STG; s++) {
        aAbase[s] = smem_u32(sA[s]);
        aBbase[s] = smem_u32(sB[s]);
    }
    // hoisted per-thread A source pointers + bounds predicates
    const float* aSrc[4];
    int okA[4];
    #pragma unroll
    for (int i = 0; i < 4; i++) {
        int row = arow + i * 32;
        aSrc[i] = X + (size_t)(bm + row) * INC + ac4;
        okA[i]  = (bm + row < NN) ? 16 : 0;
    }
    const float* bSrc[4];
    #pragma unroll
    for (int i = 0; i < 4; i++)
        bSrc[i] = W + (size_t)(brow + i * 8) * HIDD + bc4;

    wmma::fragment<wmma::accumulator, 16, 16, 8, float> acc[4][2];
    #pragma unroll
    for (int i = 0; i < 4; i++)
        #pragma unroll
        for (int j = 0; j < 2; j++)
            wmma::fill_fragment(acc[i][j], 0.0f);

    auto prefetch = [&](int st, int k0) {
        #pragma unroll
        for (int i = 0; i < 4; i++)
            cp_async16(aAbase[st] + (uint32_t)((arow + i * 32) * LDA + ac4) * 4,
                       aSrc[i] + k0, okA[i]);
        #pragma unroll
        for (int i = 0; i < 4; i++)
            cp_async16(aBbase[st] + (uint32_t)((brow + i * 8) * LDB + bc4) * 4,
                       bSrc[i] + (size_t)k0 * HIDD, 16);
    };

    prefetch(0, 0);  CP_COMMIT();
    prefetch(1, 32); CP_COMMIT();

    for (int c = 0; c < NC; c++) {
        if (c < NC - 1) { CP_WAIT(1); } else { CP_WAIT(0); }
        __syncthreads();
        // prefetch AFTER the barrier: all warps have finished MMA(c-1) on
        // buffer (c-1)%3 == (c+2)%3, so refilling it here is race-free.
        if (c + 2 < NC) {
            prefetch((c + 2) % STG, (c + 2) * 32);
            CP_COMMIT();
        }

        const float* cA = sA[c % STG];
        const float* cB = sB[c % STG];
        #pragma unroll
        for (int ks = 0; ks < 4; ks++) {
            wmma::fragment<wmma::matrix_a, 16, 16, 8,
                           wmma::precision::tf32, wmma::row_major> af[4];
            wmma::fragment<wmma::matrix_b, 16, 16, 8,
                           wmma::precision::tf32, wmma::row_major> bf[2];
            #pragma unroll
            for (int i = 0; i < 4; i++) {
                wmma::load_matrix_sync(af[i],
                    cA + (wr * 64 + i * 16) * LDA + ks * 8, LDA);
                #pragma unroll
                for (int t = 0; t < af[i].num_elements; t++)
                    af[i].x[t] = wmma::__float_to_tf32(af[i].x[t]);
            }
            #pragma unroll
            for (int j = 0; j < 2; j++) {
                wmma::load_matrix_sync(bf[j],
                    cB + (ks * 8) * LDB + wc * 32 + j * 16, LDB);
                #pragma unroll
                for (int t = 0; t < bf[j].num_elements; t++)
                    bf[j].x[t] = wmma::__float_to_tf32(bf[j].x[t]);
            }
            #pragma unroll
            for (int i = 0; i < 4; i++)
                #pragma unroll
                for (int j = 0; j < 2; j++)
                    wmma::mma_sync(acc[i][j], af[i], bf[j], acc[i][j]);
        }
    }

    // epilogue: store to g_hs (padded -> overhang rows land in scratch)
    #pragma unroll
    for (int i = 0; i < 4; i++) {
        int row = bm + wr * 64 + i * 16;
        #pragma unroll
        for (int j = 0; j < 2; j++) {
            int col = wc * 32 + j * 16;
            wmma::store_matrix_sync(g_hs + (size_t)row * HIDD + col,
                                    acc[i][j], HIDD, wmma::mem_row_major);
        }
    }
}

// -------- gather-reduce: one warp per destination node --------
// out[d] = dinv[d] * ( sum_src h[src]*dinv[src]  +  h[d]*dinv[d] )
__global__ void gather_kernel(float* __restrict__ out) {
    int gw = (blockIdx.x * blockDim.x + threadIdx.x) >> 5;
    int lane = threadIdx.x & 31;
    if (gw >= NN) return;
    const float4* hs4 = (const float4*)g_hs;
    int s0 = g_start[gw], s1 = g_start[gw + 1];
    float dself = g_dinv[gw];
    float4 h = hs4[(size_t)gw * 32 + lane];
    float4 acc = make_float4(h.x * dself, h.y * dself, h.z * dself, h.w * dself);
    int src_n = (s0 < s1) ? __ldg(&g_srcbuf[s0]) : 0;
    for (int j = s0; j < s1; j++) {
        int src = src_n;
        if (j + 1 < s1) src_n = __ldg(&g_srcbuf[j + 1]);   // hide idx->data dep
        float ds = __ldg(&g_dinv[src]);
        float4 v = hs4[(size_t)src * 32 + lane];
        acc.x = fmaf(v.x, ds, acc.x);
        acc.y = fmaf(v.y, ds, acc.y);
        acc.z = fmaf(v.z, ds, acc.z);
        acc.w = fmaf(v.w, ds, acc.w);
    }
    ((float4*)out)[(size_t)gw * 32 + lane] =
        make_float4(acc.x * dself, acc.y * dself, acc.z * dself, acc.w * dself);
}

extern "C" void kernel_launch(void* const* d_in, const int* in_sizes, int n_in,
                              void* d_out, int out_size) {
    const float* X  = (const float*)d_in[0];
    const float* W  = (const float*)d_in[1];
    const int*   ei = (const int*)d_in[2];
    float* out = (float*)d_out;

    cudaFuncSetAttribute(gemm_wmma_kernel,
                         cudaFuncAttributeMaxDynamicSharedMemorySize, GEMM_SMEM);

    init_kernel     <<<(NN + 255) / 256, 256>>>();
    count_kernel    <<<(NE + 255) / 256, 256>>>(ei);
    dinv_kernel     <<<(NN + 255) / 256, 256>>>();
    blocksum_kernel <<<NB, 1024>>>();
    bscan_kernel    <<<1, 128>>>();
    bapply_kernel   <<<NB, 1024>>>();
    fill_kernel     <<<(NE + 255) / 256, 256>>>(ei);
    gemm_wmma_kernel<<<(NN + 127) / 128, 256, GEMM_SMEM>>>(X, W);
    gather_kernel   <<<(NN * 32 + 255) / 256, 256>>>(out);
}

// round 11
// speedup vs baseline: 1.0271x; 1.0271x over previous
#include <cuda_runtime.h>
#include <mma.h>
#include <stdint.h>

using namespace nvcuda;

#define NN   100000
#define INC  1024
#define HIDD 128
#define NE   1600000
#define NB   98          // ceil(NN/1024)
#define NNPAD 100096     // NN rounded up to 128 (GEMM overhang scratch)

// -------- scratch (device globals; no allocations allowed) --------
__device__ float g_hs[(size_t)NNPAD * HIDD];  // h = X @ W (unscaled), padded
__device__ float g_dinv[NN];
__device__ int   g_cnt[NN];
__device__ int   g_start[NN + 1];
__device__ int   g_cursor[NN];
__device__ int   g_srcbuf[NE];
__device__ int   g_bsum[NB];
__device__ int   g_boff[NB];

// ===================== graph-prep kernels =====================
__global__ void init_kernel() {
    int i = blockIdx.x * blockDim.x + threadIdx.x;
    if (i < NN) { g_cnt[i] = 0; g_cursor[i] = 0; }
}

__global__ void count_kernel(const int* __restrict__ ei) {
    int e = blockIdx.x * blockDim.x + threadIdx.x;
    if (e < NE) {
        int c = ei[NE + e];
        if ((unsigned)c < NN) atomicAdd(&g_cnt[c], 1);
    }
}

__global__ void dinv_kernel() {
    int i = blockIdx.x * blockDim.x + threadIdx.x;
    if (i < NN) g_dinv[i] = rsqrtf((float)g_cnt[i] + 1.0f);
}

// ---- decoupled 3-pass scan of g_cnt -> g_start (exclusive, len NN+1) ----
__global__ void blocksum_kernel() {
    __shared__ int ws[32];
    int i = blockIdx.x * 1024 + threadIdx.x;
    int lane = threadIdx.x & 31, wid = threadIdx.x >> 5;
    int v = (i < NN) ? g_cnt[i] : 0;
    #pragma unroll
    for (int off = 16; off > 0; off >>= 1)
        v += __shfl_down_sync(0xffffffff, v, off);
    if (lane == 0) ws[wid] = v;
    __syncthreads();
    if (wid == 0) {
        int s = ws[lane];
        #pragma unroll
        for (int off = 16; off > 0; off >>= 1)
            s += __shfl_down_sync(0xffffffff, s, off);
        if (lane == 0) g_bsum[blockIdx.x] = s;
    }
}

__global__ void bscan_kernel() {   // 1 block, 128 threads over NB=98
    __shared__ int wsum[4];
    int t = threadIdx.x, lane = t & 31, w = t >> 5;
    int v = (t < NB) ? g_bsum[t] : 0;
    int x = v;
    #pragma unroll
    for (int off = 1; off < 32; off <<= 1) {
        int y = __shfl_up_sync(0xffffffff, x, off);
        if (lane >= off) x += y;
    }
    if (lane == 31) wsum[w] = x;
    __syncthreads();
    if (t == 0) {
        int a = 0;
        #pragma unroll
        for (int j = 0; j < 4; j++) { int tmp = wsum[j]; wsum[j] = a; a += tmp; }
    }
    __syncthreads();
    if (t < NB) g_boff[t] = x - v + wsum[w];   // exclusive prefix
}

__global__ void bapply_kernel() {
    __shared__ int ws[32];
    int i = blockIdx.x * 1024 + threadIdx.x;
    int lane = threadIdx.x & 31, wid = threadIdx.x >> 5;
    int v = (i < NN) ? g_cnt[i] : 0;
    int x = v;
    #pragma unroll
    for (int off = 1; off < 32; off <<= 1) {
        int y = __shfl_up_sync(0xffffffff, x, off);
        if (lane >= off) x += y;
    }
    if (lane == 31) ws[wid] = x;
    __syncthreads();
    if (wid == 0) {
        int w = ws[lane];
        #pragma unroll
        for (int off = 1; off < 32; off <<= 1) {
            int y = __shfl_up_sync(0xffffffff, w, off);
            if (lane >= off) w += y;
        }
        ws[lane] = w;
    }
    __syncthreads();
    int incl = x + (wid > 0 ? ws[wid - 1] : 0) + g_boff[blockIdx.x];
    if (i < NN) g_start[i + 1] = incl;
    if (i == 0) g_start[0] = 0;
}

__global__ void fill_kernel(const int* __restrict__ ei) {
    int e = blockIdx.x * blockDim.x + threadIdx.x;
    if (e < NE) {
        int r = ei[e];
        int c = ei[NE + e];
        if ((unsigned)c < NN && (unsigned)r < NN) {
            int pos = atomicAdd(&g_cursor[c], 1);
            g_srcbuf[g_start[c] + pos] = r;
        }
    }
}

// ==== GEMM via WMMA tf32 + cp.async 2-stage, ONE barrier per K-chunk ====
// BM=128, BN=128, BK=32, 256 threads (8 warps: 2x4, each warp 64x32).
#define LDA 36     // 32 + 4 pad
#define LDB 136    // 128 + 8 pad
#define ASZ (128 * LDA)
#define BSZ (32 * LDB)
#define NC  (INC / 32)   // 32 K-chunks
#define GEMM_SMEM ((2 * ASZ + 2 * BSZ) * 4)   // 71680 bytes -> 3 CTAs/SM

__device__ __forceinline__ uint32_t smem_u32(const void* p) {
    uint32_t a;
    asm("{ .reg .u64 t; cvta.to.shared.u64 t, %1; cvt.u32.u64 %0, t; }"
        : "=r"(a) : "l"(p));
    return a;
}
__device__ __forceinline__ void cp_async16(uint32_t dst, const void* src, int src_bytes) {
    asm volatile("cp.async.cg.shared.global [%0], [%1], 16, %2;"
                 :: "r"(dst), "l"(src), "r"(src_bytes));
}
#define CP_COMMIT() asm volatile("cp.async.commit_group;" ::: "memory")
#define CP_WAIT(N)  asm volatile("cp.async.wait_group %0;" :: "n"(N) : "memory")

__global__ __launch_bounds__(256)
void gemm_wmma_kernel(const float* __restrict__ X, const float* __restrict__ W) {
    extern __shared__ __align__(16) float smem[];
    float* sA[2] = { smem, smem + ASZ };
    float* sB[2] = { smem + 2 * ASZ, smem + 2 * ASZ + BSZ };

    const int tid = threadIdx.x;
    const int wid = tid >> 5;
    const int wr = wid >> 2;          // 0..1  (64-row band)
    const int wc = wid & 3;           // 0..3  (32-col band)
    const int bm = blockIdx.x * 128;

    const int arow = tid >> 3,  ac4 = (tid & 7) * 4;    // +32 rows per i
    const int brow = tid >> 5,  bc4 = (tid & 31) * 4;   // +8  rows per i
    uint32_t aAbase[2] = { smem_u32(sA[0]), smem_u32(sA[1]) };
    uint32_t aBbase[2] = { smem_u32(sB[0]), smem_u32(sB[1]) };

    // hoisted per-thread source pointers + bounds predicates
    const float* aSrc[4];
    int okA[4];
    #pragma unroll
    for (int i = 0; i < 4; i++) {
        int row = arow + i * 32;
        aSrc[i] = X + (size_t)(bm + row) * INC + ac4;
        okA[i]  = (bm + row < NN) ? 16 : 0;
    }
    const float* bSrc[4];
    #pragma unroll
    for (int i = 0; i < 4; i++)
        bSrc[i] = W + (size_t)(brow + i * 8) * HIDD + bc4;

    wmma::fragment<wmma::accumulator, 16, 16, 8, float> acc[4][2];
    #pragma unroll
    for (int i = 0; i < 4; i++)
        #pragma unroll
        for (int j = 0; j < 2; j++)
            wmma::fill_fragment(acc[i][j], 0.0f);

    auto prefetch = [&](int st, int k0) {
        #pragma unroll
        for (int i = 0; i < 4; i++)
            cp_async16(aAbase[st] + (uint32_t)((arow + i * 32) * LDA + ac4) * 4,
                       aSrc[i] + k0, okA[i]);
        #pragma unroll
        for (int i = 0; i < 4; i++)
            cp_async16(aBbase[st] + (uint32_t)((brow + i * 8) * LDB + bc4) * 4,
                       bSrc[i] + (size_t)k0 * HIDD, 16);
    };

    prefetch(0, 0);
    CP_COMMIT();

    for (int c = 0; c < NC; c++) {
        int st = c & 1;
        CP_WAIT(0);            // chunk c resident (only group in flight)
        __syncthreads();       // ...and every warp done with MMA(c-1) on st^1
        if (c + 1 < NC) {
            prefetch(st ^ 1, (c + 1) * 32);   // refill st^1: race-free (barrier)
            CP_COMMIT();
        }

        const float* cA = sA[st];
        const float* cB = sB[st];
        #pragma unroll
        for (int ks = 0; ks < 4; ks++) {
            wmma::fragment<wmma::matrix_a, 16, 16, 8,
                           wmma::precision::tf32, wmma::row_major> af[4];
            wmma::fragment<wmma::matrix_b, 16, 16, 8,
                           wmma::precision::tf32, wmma::row_major> bf[2];
            #pragma unroll
            for (int i = 0; i < 4; i++) {
                wmma::load_matrix_sync(af[i],
                    cA + (wr * 64 + i * 16) * LDA + ks * 8, LDA);
                #pragma unroll
                for (int t = 0; t < af[i].num_elements; t++)
                    af[i].x[t] = wmma::__float_to_tf32(af[i].x[t]);
            }
            #pragma unroll
            for (int j = 0; j < 2; j++) {
                wmma::load_matrix_sync(bf[j],
                    cB + (ks * 8) * LDB + wc * 32 + j * 16, LDB);
                #pragma unroll
                for (int t = 0; t < bf[j].num_elements; t++)
                    bf[j].x[t] = wmma::__float_to_tf32(bf[j].x[t]);
            }
            #pragma unroll
            for (int i = 0; i < 4; i++)
                #pragma unroll
                for (int j = 0; j < 2; j++)
                    wmma::mma_sync(acc[i][j], af[i], bf[j], acc[i][j]);
        }
    }

    // epilogue: store to g_hs (padded -> overhang rows land in scratch)
    #pragma unroll
    for (int i = 0; i < 4; i++) {
        int row = bm + wr * 64 + i * 16;
        #pragma unroll
        for (int j = 0; j < 2; j++) {
            int col = wc * 32 + j * 16;
            wmma::store_matrix_sync(g_hs + (size_t)row * HIDD + col,
                                    acc[i][j], HIDD, wmma::mem_row_major);
        }
    }
}

// -------- gather-reduce: one warp per destination node, 2-edge unroll --------
// out[d] = dinv[d] * ( sum_src h[src]*dinv[src]  +  h[d]*dinv[d] )
__global__ void gather_kernel(float* __restrict__ out) {
    int gw = (blockIdx.x * blockDim.x + threadIdx.x) >> 5;
    int lane = threadIdx.x & 31;
    if (gw >= NN) return;
    const float4* hs4 = (const float4*)g_hs;
    int s0 = g_start[gw], s1 = g_start[gw + 1];
    float dself = g_dinv[gw];
    float4 h = hs4[(size_t)gw * 32 + lane];
    float4 acc0 = make_float4(h.x * dself, h.y * dself, h.z * dself, h.w * dself);
    float4 acc1 = make_float4(0.f, 0.f, 0.f, 0.f);
    int j = s0;
    for (; j + 1 < s1; j += 2) {
        int src0 = __ldg(&g_srcbuf[j]);
        int src1 = __ldg(&g_srcbuf[j + 1]);
        float ds0 = __ldg(&g_dinv[src0]);
        float ds1 = __ldg(&g_dinv[src1]);
        float4 v0 = hs4[(size_t)src0 * 32 + lane];
        float4 v1 = hs4[(size_t)src1 * 32 + lane];
        acc0.x = fmaf(v0.x, ds0, acc0.x);
        acc0.y = fmaf(v0.y, ds0, acc0.y);
        acc0.z = fmaf(v0.z, ds0, acc0.z);
        acc0.w = fmaf(v0.w, ds0, acc0.w);
        acc1.x = fmaf(v1.x, ds1, acc1.x);
        acc1.y = fmaf(v1.y, ds1, acc1.y);
        acc1.z = fmaf(v1.z, ds1, acc1.z);
        acc1.w = fmaf(v1.w, ds1, acc1.w);
    }
    if (j < s1) {
        int src = __ldg(&g_srcbuf[j]);
        float ds = __ldg(&g_dinv[src]);
        float4 v = hs4[(size_t)src * 32 + lane];
        acc0.x = fmaf(v.x, ds, acc0.x);
        acc0.y = fmaf(v.y, ds, acc0.y);
        acc0.z = fmaf(v.z, ds, acc0.z);
        acc0.w = fmaf(v.w, ds, acc0.w);
    }
    float4 r;
    r.x = (acc0.x + acc1.x) * dself;
    r.y = (acc0.y + acc1.y) * dself;
    r.z = (acc0.z + acc1.z) * dself;
    r.w = (acc0.w + acc1.w) * dself;
    ((float4*)out)[(size_t)gw * 32 + lane] = r;
}

extern "C" void kernel_launch(void* const* d_in, const int* in_sizes, int n_in,
                              void* d_out, int out_size) {
    const float* X  = (const float*)d_in[0];
    const float* W  = (const float*)d_in[1];
    const int*   ei = (const int*)d_in[2];
    float* out = (float*)d_out;

    cudaFuncSetAttribute(gemm_wmma_kernel,
                         cudaFuncAttributeMaxDynamicSharedMemorySize, GEMM_SMEM);

    init_kernel     <<<(NN + 255) / 256, 256>>>();
    count_kernel    <<<(NE + 255) / 256, 256>>>(ei);
    dinv_kernel     <<<(NN + 255) / 256, 256>>>();
    blocksum_kernel <<<NB, 1024>>>();
    bscan_kernel    <<<1, 128>>>();
    bapply_kernel   <<<NB, 1024>>>();
    fill_kernel     <<<(NE + 255) / 256, 256>>>(ei);
    gemm_wmma_kernel<<<(NN + 127) / 128, 256, GEMM_SMEM>>>(X, W);
    gather_kernel   <<<(NN * 32 + 255) / 256, 256>>>(out);
}

// round 12
// speedup vs baseline: 1.0472x; 1.0196x over previous
#include <cuda_runtime.h>
#include <mma.h>
#include <stdint.h>

using namespace nvcuda;

#define NN   100000
#define INC  1024
#define HIDD 128
#define NE   1600000
#define NB   98          // ceil(NN/1024)
#define NNPAD 100096     // NN rounded up to 128 (GEMM overhang scratch)

// -------- scratch (device globals; no allocations allowed) --------
__device__ float g_hs[(size_t)NNPAD * HIDD];  // h = X @ W (unscaled), padded
__device__ float g_dinv[NN];
__device__ int   g_cnt[NN];
__device__ int   g_start[NN + 1];
__device__ int   g_cursor[NN];
__device__ int   g_srcbuf[NE];
__device__ int   g_bsum[NB];
__device__ int   g_boff[NB];

// ===================== graph-prep kernels =====================
__global__ void init_kernel() {
    int i = blockIdx.x * blockDim.x + threadIdx.x;
    if (i < NN) { g_cnt[i] = 0; g_cursor[i] = 0; }
}

__global__ void count_kernel(const int* __restrict__ ei) {
    int e = blockIdx.x * blockDim.x + threadIdx.x;
    if (e < NE) {
        int c = ei[NE + e];
        if ((unsigned)c < NN) atomicAdd(&g_cnt[c], 1);
    }
}

// ---- decoupled 3-pass scan of g_cnt -> g_start (exclusive, len NN+1) ----
__global__ void blocksum_kernel() {
    __shared__ int ws[32];
    int i = blockIdx.x * 1024 + threadIdx.x;
    int lane = threadIdx.x & 31, wid = threadIdx.x >> 5;
    int v = (i < NN) ? g_cnt[i] : 0;
    #pragma unroll
    for (int off = 16; off > 0; off >>= 1)
        v += __shfl_down_sync(0xffffffff, v, off);
    if (lane == 0) ws[wid] = v;
    __syncthreads();
    if (wid == 0) {
        int s = ws[lane];
        #pragma unroll
        for (int off = 16; off > 0; off >>= 1)
            s += __shfl_down_sync(0xffffffff, s, off);
        if (lane == 0) g_bsum[blockIdx.x] = s;
    }
}

__global__ void bscan_kernel() {   // 1 block, 128 threads over NB=98
    __shared__ int wsum[4];
    int t = threadIdx.x, lane = t & 31, w = t >> 5;
    int v = (t < NB) ? g_bsum[t] : 0;
    int x = v;
    #pragma unroll
    for (int off = 1; off < 32; off <<= 1) {
        int y = __shfl_up_sync(0xffffffff, x, off);
        if (lane >= off) x += y;
    }
    if (lane == 31) wsum[w] = x;
    __syncthreads();
    if (t == 0) {
        int a = 0;
        #pragma unroll
        for (int j = 0; j < 4; j++) { int tmp = wsum[j]; wsum[j] = a; a += tmp; }
    }
    __syncthreads();
    if (t < NB) g_boff[t] = x - v + wsum[w];   // exclusive prefix
}

// bapply also computes dinv (fused; both read g_cnt)
__global__ void bapply_kernel() {
    __shared__ int ws[32];
    int i = blockIdx.x * 1024 + threadIdx.x;
    int lane = threadIdx.x & 31, wid = threadIdx.x >> 5;
    int v = (i < NN) ? g_cnt[i] : 0;
    if (i < NN) g_dinv[i] = rsqrtf((float)v + 1.0f);
    int x = v;
    #pragma unroll
    for (int off = 1; off < 32; off <<= 1) {
        int y = __shfl_up_sync(0xffffffff, x, off);
        if (lane >= off) x += y;
    }
    if (lane == 31) ws[wid] = x;
    __syncthreads();
    if (wid == 0) {
        int w = ws[lane];
        #pragma unroll
        for (int off = 1; off < 32; off <<= 1) {
            int y = __shfl_up_sync(0xffffffff, w, off);
            if (lane >= off) w += y;
        }
        ws[lane] = w;
    }
    __syncthreads();
    int incl = x + (wid > 0 ? ws[wid - 1] : 0) + g_boff[blockIdx.x];
    if (i < NN) g_start[i + 1] = incl;
    if (i == 0) g_start[0] = 0;
}

__global__ void fill_kernel(const int* __restrict__ ei) {
    int e = blockIdx.x * blockDim.x + threadIdx.x;
    if (e < NE) {
        int r = ei[e];
        int c = ei[NE + e];
        if ((unsigned)c < NN && (unsigned)r < NN) {
            int pos = atomicAdd(&g_cursor[c], 1);
            g_srcbuf[g_start[c] + pos] = r;
        }
    }
}

// ==== GEMM via WMMA tf32 + cp.async 2-stage pipeline (R9 structure) ====
// BM=128, BN=128, BK=32, 256 threads (8 warps: 2x4, each warp 64x32).
#define LDA 36     // 32 + 4 pad
#define LDB 136    // 128 + 8 pad
#define ASZ (128 * LDA)
#define BSZ (32 * LDB)
#define NC  (INC / 32)   // 32 K-chunks
#define GEMM_SMEM ((2 * ASZ + 2 * BSZ) * 4)   // 71680 bytes -> 3 CTAs/SM

__device__ __forceinline__ uint32_t smem_u32(const void* p) {
    uint32_t a;
    asm("{ .reg .u64 t; cvta.to.shared.u64 t, %1; cvt.u32.u64 %0, t; }"
        : "=r"(a) : "l"(p));
    return a;
}
__device__ __forceinline__ void cp_async16(uint32_t dst, const void* src, int src_bytes) {
    asm volatile("cp.async.cg.shared.global [%0], [%1], 16, %2;"
                 :: "r"(dst), "l"(src), "r"(src_bytes));
}
#define CP_COMMIT() asm volatile("cp.async.commit_group;" ::: "memory")
#define CP_WAIT(N)  asm volatile("cp.async.wait_group %0;" :: "n"(N) : "memory")

__global__ __launch_bounds__(256)
void gemm_wmma_kernel(const float* __restrict__ X, const float* __restrict__ W) {
    extern __shared__ __align__(16) float smem[];
    float* sA[2] = { smem, smem + ASZ };
    float* sB[2] = { smem + 2 * ASZ, smem + 2 * ASZ + BSZ };

    const int tid = threadIdx.x;
    const int wid = tid >> 5;
    const int wr = wid >> 2;          // 0..1  (64-row band)
    const int wc = wid & 3;           // 0..3  (32-col band)
    const int bm = blockIdx.x * 128;

    const int arow = tid >> 3,  ac4 = (tid & 7) * 4;    // +32 rows per i
    const int brow = tid >> 5,  bc4 = (tid & 31) * 4;   // +8  rows per i
    uint32_t aAbase[2] = { smem_u32(sA[0]), smem_u32(sA[1]) };
    uint32_t aBbase[2] = { smem_u32(sB[0]), smem_u32(sB[1]) };

    // hoisted per-thread source pointers + bounds predicates
    const float* aSrc[4];
    int okA[4];
    #pragma unroll
    for (int i = 0; i < 4; i++) {
        int row = arow + i * 32;
        aSrc[i] = X + (size_t)(bm + row) * INC + ac4;
        okA[i]  = (bm + row < NN) ? 16 : 0;
    }
    const float* bSrc[4];
    #pragma unroll
    for (int i = 0; i < 4; i++)
        bSrc[i] = W + (size_t)(brow + i * 8) * HIDD + bc4;

    wmma::fragment<wmma::accumulator, 16, 16, 8, float> acc[4][2];
    #pragma unroll
    for (int i = 0; i < 4; i++)
        #pragma unroll
        for (int j = 0; j < 2; j++)
            wmma::fill_fragment(acc[i][j], 0.0f);

    auto prefetch = [&](int st, int k0) {
        #pragma unroll
        for (int i = 0; i < 4; i++)
            cp_async16(aAbase[st] + (uint32_t)((arow + i * 32) * LDA + ac4) * 4,
                       aSrc[i] + k0, okA[i]);
        #pragma unroll
        for (int i = 0; i < 4; i++)
            cp_async16(aBbase[st] + (uint32_t)((brow + i * 8) * LDB + bc4) * 4,
                       bSrc[i] + (size_t)k0 * HIDD, 16);
    };

    prefetch(0, 0);
    CP_COMMIT();

    for (int c = 0; c < NC; c++) {
        int st = c & 1;
        if (c + 1 < NC) {
            prefetch(st ^ 1, (c + 1) * 32);   // issue BEFORE wait: depth-2 pipeline
            CP_COMMIT();
            CP_WAIT(1);                       // chunk c resident
        } else {
            CP_WAIT(0);
        }
        __syncthreads();

        const float* cA = sA[st];
        const float* cB = sB[st];
        #pragma unroll
        for (int ks = 0; ks < 4; ks++) {
            wmma::fragment<wmma::matrix_a, 16, 16, 8,
                           wmma::precision::tf32, wmma::row_major> af[4];
            wmma::fragment<wmma::matrix_b, 16, 16, 8,
                           wmma::precision::tf32, wmma::row_major> bf[2];
            #pragma unroll
            for (int i = 0; i < 4; i++) {
                wmma::load_matrix_sync(af[i],
                    cA + (wr * 64 + i * 16) * LDA + ks * 8, LDA);
                #pragma unroll
                for (int t = 0; t < af[i].num_elements; t++)
                    af[i].x[t] = wmma::__float_to_tf32(af[i].x[t]);
            }
            #pragma unroll
            for (int j = 0; j < 2; j++) {
                wmma::load_matrix_sync(bf[j],
                    cB + (ks * 8) * LDB + wc * 32 + j * 16, LDB);
                #pragma unroll
                for (int t = 0; t < bf[j].num_elements; t++)
                    bf[j].x[t] = wmma::__float_to_tf32(bf[j].x[t]);
            }
            #pragma unroll
            for (int i = 0; i < 4; i++)
                #pragma unroll
                for (int j = 0; j < 2; j++)
                    wmma::mma_sync(acc[i][j], af[i], bf[j], acc[i][j]);
        }
        __syncthreads();   // all warps done with stage st before it is refilled
    }

    // epilogue: store to g_hs (padded -> overhang rows land in scratch)
    #pragma unroll
    for (int i = 0; i < 4; i++) {
        int row = bm + wr * 64 + i * 16;
        #pragma unroll
        for (int j = 0; j < 2; j++) {
            int col = wc * 32 + j * 16;
            wmma::store_matrix_sync(g_hs + (size_t)row * HIDD + col,
                                    acc[i][j], HIDD, wmma::mem_row_major);
        }
    }
}

// -------- gather-reduce: one warp per destination node, 2-edge unroll --------
// out[d] = dinv[d] * ( sum_src h[src]*dinv[src]  +  h[d]*dinv[d] )
__global__ void gather_kernel(float* __restrict__ out) {
    int gw = (blockIdx.x * blockDim.x + threadIdx.x) >> 5;
    int lane = threadIdx.x & 31;
    if (gw >= NN) return;
    const float4* hs4 = (const float4*)g_hs;
    int s0 = g_start[gw], s1 = g_start[gw + 1];
    float dself = g_dinv[gw];
    float4 h = hs4[(size_t)gw * 32 + lane];
    float4 acc0 = make_float4(h.x * dself, h.y * dself, h.z * dself, h.w * dself);
    float4 acc1 = make_float4(0.f, 0.f, 0.f, 0.f);
    int j = s0;
    for (; j + 1 < s1; j += 2) {
        int src0 = __ldg(&g_srcbuf[j]);
        int src1 = __ldg(&g_srcbuf[j + 1]);
        float ds0 = __ldg(&g_dinv[src0]);
        float ds1 = __ldg(&g_dinv[src1]);
        float4 v0 = hs4[(size_t)src0 * 32 + lane];
        float4 v1 = hs4[(size_t)src1 * 32 + lane];
        acc0.x = fmaf(v0.x, ds0, acc0.x);
        acc0.y = fmaf(v0.y, ds0, acc0.y);
        acc0.z = fmaf(v0.z, ds0, acc0.z);
        acc0.w = fmaf(v0.w, ds0, acc0.w);
        acc1.x = fmaf(v1.x, ds1, acc1.x);
        acc1.y = fmaf(v1.y, ds1, acc1.y);
        acc1.z = fmaf(v1.z, ds1, acc1.z);
        acc1.w = fmaf(v1.w, ds1, acc1.w);
    }
    if (j < s1) {
        int src = __ldg(&g_srcbuf[j]);
        float ds = __ldg(&g_dinv[src]);
        float4 v = hs4[(size_t)src * 32 + lane];
        acc0.x = fmaf(v.x, ds, acc0.x);
        acc0.y = fmaf(v.y, ds, acc0.y);
        acc0.z = fmaf(v.z, ds, acc0.z);
        acc0.w = fmaf(v.w, ds, acc0.w);
    }
    float4 r;
    r.x = (acc0.x + acc1.x) * dself;
    r.y = (acc0.y + acc1.y) * dself;
    r.z = (acc0.z + acc1.z) * dself;
    r.w = (acc0.w + acc1.w) * dself;
    ((float4*)out)[(size_t)gw * 32 + lane] = r;
}

extern "C" void kernel_launch(void* const* d_in, const int* in_sizes, int n_in,
                              void* d_out, int out_size) {
    const float* X  = (const float*)d_in[0];
    const float* W  = (const float*)d_in[1];
    const int*   ei = (const int*)d_in[2];
    float* out = (float*)d_out;

    cudaFuncSetAttribute(gemm_wmma_kernel,
                         cudaFuncAttributeMaxDynamicSharedMemorySize, GEMM_SMEM);

    init_kernel     <<<(NN + 255) / 256, 256>>>();
    count_kernel    <<<(NE + 255) / 256, 256>>>(ei);
    blocksum_kernel <<<NB, 1024>>>();
    bscan_kernel    <<<1, 128>>>();
    bapply_kernel   <<<NB, 1024>>>();
    fill_kernel     <<<(NE + 255) / 256, 256>>>(ei);
    gemm_wmma_kernel<<<(NN + 127) / 128, 256, GEMM_SMEM>>>(X, W);
    gather_kernel   <<<(NN * 32 + 255) / 256, 256>>>(out);
}

// round 14
// speedup vs baseline: 1.0503x; 1.0030x over previous
#include <cuda_runtime.h>
#include <cuda_fp16.h>
#include <mma.h>
#include <stdint.h>

using namespace nvcuda;

#define NN   100000
#define INC  1024
#define HIDD 128
#define NE   1600000
#define NB   98          // ceil(NN/1024)
#define NNPAD 100096     // NN rounded up to 128 (GEMM overhang scratch)

// -------- scratch (device globals; no allocations allowed) --------
__device__ uint2 g_hsb[(size_t)NNPAD * 32];   // h*dinv as fp16, 64 half2/row (25.6MB)
__device__ float g_dinv[NN];
__device__ int   g_cnt[NN];
__device__ int   g_start[NN + 1];
__device__ int   g_cursor[NN];
__device__ int   g_srcbuf[NE];
__device__ int   g_bsum[NB];
__device__ int   g_boff[NB];

// ===================== graph-prep kernels =====================
__global__ void init_kernel() {
    int i = blockIdx.x * blockDim.x + threadIdx.x;
    if (i < NN) { g_cnt[i] = 0; g_cursor[i] = 0; }
}

__global__ void count_kernel(const int* __restrict__ ei) {
    int e = blockIdx.x * blockDim.x + threadIdx.x;
    if (e < NE) {
        int c = ei[NE + e];
        if ((unsigned)c < NN) atomicAdd(&g_cnt[c], 1);
    }
}

// ---- decoupled 3-pass scan of g_cnt -> g_start (exclusive, len NN+1) ----
__global__ void blocksum_kernel() {
    __shared__ int ws[32];
    int i = blockIdx.x * 1024 + threadIdx.x;
    int lane = threadIdx.x & 31, wid = threadIdx.x >> 5;
    int v = (i < NN) ? g_cnt[i] : 0;
    #pragma unroll
    for (int off = 16; off > 0; off >>= 1)
        v += __shfl_down_sync(0xffffffff, v, off);
    if (lane == 0) ws[wid] = v;
    __syncthreads();
    if (wid == 0) {
        int s = ws[lane];
        #pragma unroll
        for (int off = 16; off > 0; off >>= 1)
            s += __shfl_down_sync(0xffffffff, s, off);
        if (lane == 0) g_bsum[blockIdx.x] = s;
    }
}

__global__ void bscan_kernel() {   // 1 block, 128 threads over NB=98
    __shared__ int wsum[4];
    int t = threadIdx.x, lane = t & 31, w = t >> 5;
    int v = (t < NB) ? g_bsum[t] : 0;
    int x = v;
    #pragma unroll
    for (int off = 1; off < 32; off <<= 1) {
        int y = __shfl_up_sync(0xffffffff, x, off);
        if (lane >= off) x += y;
    }
    if (lane == 31) wsum[w] = x;
    __syncthreads();
    if (t == 0) {
        int a = 0;
        #pragma unroll
        for (int j = 0; j < 4; j++) { int tmp = wsum[j]; wsum[j] = a; a += tmp; }
    }
    __syncthreads();
    if (t < NB) g_boff[t] = x - v + wsum[w];   // exclusive prefix
}

// bapply also computes dinv (fused; both read g_cnt)
__global__ void bapply_kernel() {
    __shared__ int ws[32];
    int i = blockIdx.x * 1024 + threadIdx.x;
    int lane = threadIdx.x & 31, wid = threadIdx.x >> 5;
    int v = (i < NN) ? g_cnt[i] : 0;
    if (i < NN) g_dinv[i] = rsqrtf((float)v + 1.0f);
    int x = v;
    #pragma unroll
    for (int off = 1; off < 32; off <<= 1) {
        int y = __shfl_up_sync(0xffffffff, x, off);
        if (lane >= off) x += y;
    }
    if (lane == 31) ws[wid] = x;
    __syncthreads();
    if (wid == 0) {
        int w = ws[lane];
        #pragma unroll
        for (int off = 1; off < 32; off <<= 1) {
            int y = __shfl_up_sync(0xffffffff, w, off);
            if (lane >= off) w += y;
        }
        ws[lane] = w;
    }
    __syncthreads();
    int incl = x + (wid > 0 ? ws[wid - 1] : 0) + g_boff[blockIdx.x];
    if (i < NN) g_start[i + 1] = incl;
    if (i == 0) g_start[0] = 0;
}

__global__ void fill_kernel(const int* __restrict__ ei) {
    int e = blockIdx.x * blockDim.x + threadIdx.x;
    if (e < NE) {
        int r = ei[e];
        int c = ei[NE + e];
        if ((unsigned)c < NN && (unsigned)r < NN) {
            int pos = atomicAdd(&g_cursor[c], 1);
            g_srcbuf[g_start[c] + pos] = r;
        }
    }
}

// ==== GEMM via WMMA tf32 + cp.async 2-stage pipeline; fp16 scaled epilogue ====
// BM=128, BN=128, BK=32, 256 threads (8 warps: 2x4, each warp 64x32).
#define LDA 36     // 32 + 4 pad
#define LDB 136    // 128 + 8 pad
#define ASZ (128 * LDA)
#define BSZ (32 * LDB)
#define NC  (INC / 32)   // 32 K-chunks
#define LDS 132    // epilogue staging stride (128 + 4 pad)
#define GEMM_SMEM ((2 * ASZ + 2 * BSZ) * 4)   // 71680 bytes -> 3 CTAs/SM

__device__ __forceinline__ uint32_t smem_u32(const void* p) {
    uint32_t a;
    asm("{ .reg .u64 t; cvta.to.shared.u64 t, %1; cvt.u32.u64 %0, t; }"
        : "=r"(a) : "l"(p));
    return a;
}
__device__ __forceinline__ void cp_async16(uint32_t dst, const void* src, int src_bytes) {
    asm volatile("cp.async.cg.shared.global [%0], [%1], 16, %2;"
                 :: "r"(dst), "l"(src), "r"(src_bytes));
}
#define CP_COMMIT() asm volatile("cp.async.commit_group;" ::: "memory")
#define CP_WAIT(N)  asm volatile("cp.async.wait_group %0;" :: "n"(N) : "memory")

__global__ __launch_bounds__(256)
void gemm_wmma_kernel(const float* __restrict__ X, const float* __restrict__ W) {
    extern __shared__ __align__(16) float smem[];
    float* sA[2] = { smem, smem + ASZ };
    float* sB[2] = { smem + 2 * ASZ, smem + 2 * ASZ + BSZ };

    const int tid = threadIdx.x;
    const int wid = tid >> 5;
    const int wr = wid >> 2;          // 0..1  (64-row band)
    const int wc = wid & 3;           // 0..3  (32-col band)
    const int bm = blockIdx.x * 128;

    const int arow = tid >> 3,  ac4 = (tid & 7) * 4;    // +32 rows per i
    const int brow = tid >> 5,  bc4 = (tid & 31) * 4;   // +8  rows per i
    uint32_t aAbase[2] = { smem_u32(sA[0]), smem_u32(sA[1]) };
    uint32_t aBbase[2] = { smem_u32(sB[0]), smem_u32(sB[1]) };

    const float* aSrc[4];
    int okA[4];
    #pragma unroll
    for (int i = 0; i < 4; i++) {
        int row = arow + i * 32;
        aSrc[i] = X + (size_t)(bm + row) * INC + ac4;
        okA[i]  = (bm + row < NN) ? 16 : 0;
    }
    const float* bSrc[4];
    #pragma unroll
    for (int i = 0; i < 4; i++)
        bSrc[i] = W + (size_t)(brow + i * 8) * HIDD + bc4;

    wmma::fragment<wmma::accumulator, 16, 16, 8, float> acc[4][2];
    #pragma unroll
    for (int i = 0; i < 4; i++)
        #pragma unroll
        for (int j = 0; j < 2; j++)
            wmma::fill_fragment(acc[i][j], 0.0f);

    auto prefetch = [&](int st, int k0) {
        #pragma unroll
        for (int i = 0; i < 4; i++)
            cp_async16(aAbase[st] + (uint32_t)((arow + i * 32) * LDA + ac4) * 4,
                       aSrc[i] + k0, okA[i]);
        #pragma unroll
        for (int i = 0; i < 4; i++)
            cp_async16(aBbase[st] + (uint32_t)((brow + i * 8) * LDB + bc4) * 4,
                       bSrc[i] + (size_t)k0 * HIDD, 16);
    };

    prefetch(0, 0);
    CP_COMMIT();

    for (int c = 0; c < NC; c++) {
        int st = c & 1;
        if (c + 1 < NC) {
            prefetch(st ^ 1, (c + 1) * 32);   // issue BEFORE wait: depth-2 pipeline
            CP_COMMIT();
            CP_WAIT(1);                       // chunk c resident
        } else {
            CP_WAIT(0);
        }
        __syncthreads();

        const float* cA = sA[st];
        const float* cB = sB[st];
        #pragma unroll
        for (int ks = 0; ks < 4; ks++) {
            wmma::fragment<wmma::matrix_a, 16, 16, 8,
                           wmma::precision::tf32, wmma::row_major> af[4];
            wmma::fragment<wmma::matrix_b, 16, 16, 8,
                           wmma::precision::tf32, wmma::row_major> bf[2];
            #pragma unroll
            for (int i = 0; i < 4; i++) {
                wmma::load_matrix_sync(af[i],
                    cA + (wr * 64 + i * 16) * LDA + ks * 8, LDA);
                #pragma unroll
                for (int t = 0; t < af[i].num_elements; t++)
                    af[i].x[t] = wmma::__float_to_tf32(af[i].x[t]);
            }
            #pragma unroll
            for (int j = 0; j < 2; j++) {
                wmma::load_matrix_sync(bf[j],
                    cB + (ks * 8) * LDB + wc * 32 + j * 16, LDB);
                #pragma unroll
                for (int t = 0; t < bf[j].num_elements; t++)
                    bf[j].x[t] = wmma::__float_to_tf32(bf[j].x[t]);
            }
            #pragma unroll
            for (int i = 0; i < 4; i++)
                #pragma unroll
                for (int j = 0; j < 2; j++)
                    wmma::mma_sync(acc[i][j], af[i], bf[j], acc[i][j]);
        }
        __syncthreads();   // all warps done with stage st before it is refilled
    }

    // ---- epilogue: stage fp32 -> scale by dinv[row] -> half2 -> g_hsb ----
    // pipeline buffers are dead now; reuse smem as 128 x LDS staging.
    float* stage = smem;
    #pragma unroll
    for (int i = 0; i < 4; i++)
        #pragma unroll
        for (int j = 0; j < 2; j++)
            wmma::store_matrix_sync(stage + (wr * 64 + i * 16) * LDS + wc * 32 + j * 16,
                                    acc[i][j], LDS, wmma::mem_row_major);
    __syncthreads();

    // 8192 half2 per CTA; 32 per thread; consecutive tids -> consecutive half2
    #pragma unroll
    for (int p = 0; p < 32; p++) {
        int idx  = tid + p * 256;        // 0..8191
        int row  = idx >> 6;             // 0..127
        int col2 = idx & 63;             // half2 index in row
        int grow = bm + row;
        float dv = (grow < NN) ? g_dinv[grow] : 0.0f;
        float2 v;
        v.x = stage[row * LDS + col2 * 2 + 0] * dv;
        v.y = stage[row * LDS + col2 * 2 + 1] * dv;
        __half2 h = __float22half2_rn(v);
        ((__half2*)g_hsb)[(size_t)grow * 64 + col2] = h;
    }
}

// -------- gather-reduce: one warp per destination node, 2-edge unroll --------
// hs rows carry h*dinv already:  out[d] = dinv[d] * ( sum_src hs[src] + hs[d] )
__global__ void gather_kernel(float* __restrict__ out) {
    int gw = (blockIdx.x * blockDim.x + threadIdx.x) >> 5;
    int lane = threadIdx.x & 31;
    if (gw >= NN) return;
    const uint2* hsb = (const uint2*)g_hsb;   // 32 uint2/row; lane -> cols [4*lane,4*lane+4)
    int s0 = g_start[gw], s1 = g_start[gw + 1];
    float dself = g_dinv[gw];

    auto cvt = [](uint2 r) {
        __half2 a = *(__half2*)&r.x;
        __half2 b = *(__half2*)&r.y;
        float2 fa = __half22float2(a);
        float2 fb = __half22float2(b);
        return make_float4(fa.x, fa.y, fb.x, fb.y);
    };

    float4 acc0 = cvt(__ldg(&hsb[(size_t)gw * 32 + lane]));   // self-loop term
    float4 acc1 = make_float4(0.f, 0.f, 0.f, 0.f);
    int j = s0;
    for (; j + 1 < s1; j += 2) {
        int src0 = __ldg(&g_srcbuf[j]);
        int src1 = __ldg(&g_srcbuf[j + 1]);
        float4 v0 = cvt(__ldg(&hsb[(size_t)src0 * 32 + lane]));
        float4 v1 = cvt(__ldg(&hsb[(size_t)src1 * 32 + lane]));
        acc0.x += v0.x; acc0.y += v0.y; acc0.z += v0.z; acc0.w += v0.w;
        acc1.x += v1.x; acc1.y += v1.y; acc1.z += v1.z; acc1.w += v1.w;
    }
    if (j < s1) {
        int src = __ldg(&g_srcbuf[j]);
        float4 v = cvt(__ldg(&hsb[(size_t)src * 32 + lane]));
        acc0.x += v.x; acc0.y += v.y; acc0.z += v.z; acc0.w += v.w;
    }
    float4 r;
    r.x = (acc0.x + acc1.x) * dself;
    r.y = (acc0.y + acc1.y) * dself;
    r.z = (acc0.z + acc1.z) * dself;
    r.w = (acc0.w + acc1.w) * dself;
    ((float4*)out)[(size_t)gw * 32 + lane] = r;
}

extern "C" void kernel_launch(void* const* d_in, const int* in_sizes, int n_in,
                              void* d_out, int out_size) {
    const float* X  = (const float*)d_in[0];
    const float* W  = (const float*)d_in[1];
    const int*   ei = (const int*)d_in[2];
    float* out = (float*)d_out;

    cudaFuncSetAttribute(gemm_wmma_kernel,
                         cudaFuncAttributeMaxDynamicSharedMemorySize, GEMM_SMEM);

    init_kernel     <<<(NN + 255) / 256, 256>>>();
    count_kernel    <<<(NE + 255) / 256, 256>>>(ei);
    blocksum_kernel <<<NB, 1024>>>();
    bscan_kernel    <<<1, 128>>>();
    bapply_kernel   <<<NB, 1024>>>();
    fill_kernel     <<<(NE + 255) / 256, 256>>>(ei);
    gemm_wmma_kernel<<<(NN + 127) / 128, 256, GEMM_SMEM>>>(X, W);
    gather_kernel   <<<(NN * 32 + 255) / 256, 256>>>(out);
}

// round 17
// speedup vs baseline: 2.2172x; 2.1110x over previous
#include <cuda_runtime.h>
#include <cuda_fp16.h>
#include <mma.h>
#include <stdint.h>

using namespace nvcuda;

#define NN   100000
#define INC  1024
#define HIDD 128
#define NE   1600000
#define NB   98          // ceil(NN/1024)
#define NNPAD 100096     // NN rounded up to 128 (GEMM overhang scratch)

// -------- scratch (device globals; no allocations allowed) --------
__device__ uint2  g_hsb[(size_t)NNPAD * 32];  // h*dinv as fp16, 64 half2/row (25.6MB)
__device__ __half g_wh[(size_t)INC * HIDD];   // W in fp16 (256KB)
__device__ float  g_dinv[NN];
__device__ int    g_cnt[NN];
__device__ int    g_start[NN + 1];
__device__ int    g_cursor[NN];
__device__ int    g_srcbuf[NE];
__device__ int    g_bsum[NB];
__device__ int    g_boff[NB];

// ===================== graph-prep kernels =====================
__global__ void init_kernel() {
    int i = blockIdx.x * blockDim.x + threadIdx.x;
    if (i < NN) { g_cnt[i] = 0; g_cursor[i] = 0; }
}

__global__ void count_kernel(const int* __restrict__ ei) {
    int e = blockIdx.x * blockDim.x + threadIdx.x;
    if (e < NE) {
        int c = ei[NE + e];
        if ((unsigned)c < NN) atomicAdd(&g_cnt[c], 1);
    }
}

// ---- decoupled 3-pass scan of g_cnt -> g_start (exclusive, len NN+1) ----
__global__ void blocksum_kernel() {
    __shared__ int ws[32];
    int i = blockIdx.x * 1024 + threadIdx.x;
    int lane = threadIdx.x & 31, wid = threadIdx.x >> 5;
    int v = (i < NN) ? g_cnt[i] : 0;
    #pragma unroll
    for (int off = 16; off > 0; off >>= 1)
        v += __shfl_down_sync(0xffffffff, v, off);
    if (lane == 0) ws[wid] = v;
    __syncthreads();
    if (wid == 0) {
        int s = ws[lane];
        #pragma unroll
        for (int off = 16; off > 0; off >>= 1)
            s += __shfl_down_sync(0xffffffff, s, off);
        if (lane == 0) g_bsum[blockIdx.x] = s;
    }
}

__global__ void bscan_kernel() {   // 1 block, 128 threads over NB=98
    __shared__ int wsum[4];
    int t = threadIdx.x, lane = t & 31, w = t >> 5;
    int v = (t < NB) ? g_bsum[t] : 0;
    int x = v;
    #pragma unroll
    for (int off = 1; off < 32; off <<= 1) {
        int y = __shfl_up_sync(0xffffffff, x, off);
        if (lane >= off) x += y;
    }
    if (lane == 31) wsum[w] = x;
    __syncthreads();
    if (t == 0) {
        int a = 0;
        #pragma unroll
        for (int j = 0; j < 4; j++) { int tmp = wsum[j]; wsum[j] = a; a += tmp; }
    }
    __syncthreads();
    if (t < NB) g_boff[t] = x - v + wsum[w];   // exclusive prefix
}

// bapply also computes dinv (fused; both read g_cnt)
__global__ void bapply_kernel() {
    __shared__ int ws[32];
    int i = blockIdx.x * 1024 + threadIdx.x;
    int lane = threadIdx.x & 31, wid = threadIdx.x >> 5;
    int v = (i < NN) ? g_cnt[i] : 0;
    if (i < NN) g_dinv[i] = rsqrtf((float)v + 1.0f);
    int x = v;
    #pragma unroll
    for (int off = 1; off < 32; off <<= 1) {
        int y = __shfl_up_sync(0xffffffff, x, off);
        if (lane >= off) x += y;
    }
    if (lane == 31) ws[wid] = x;
    __syncthreads();
    if (wid == 0) {
        int w = ws[lane];
        #pragma unroll
        for (int off = 1; off < 32; off <<= 1) {
            int y = __shfl_up_sync(0xffffffff, w, off);
            if (lane >= off) w += y;
        }
        ws[lane] = w;
    }
    __syncthreads();
    int incl = x + (wid > 0 ? ws[wid - 1] : 0) + g_boff[blockIdx.x];
    if (i < NN) g_start[i + 1] = incl;
    if (i == 0) g_start[0] = 0;
}

__global__ void fill_kernel(const int* __restrict__ ei) {
    int e = blockIdx.x * blockDim.x + threadIdx.x;
    if (e < NE) {
        int r = ei[e];
        int c = ei[NE + e];
        if ((unsigned)c < NN && (unsigned)r < NN) {
            int pos = atomicAdd(&g_cursor[c], 1);
            g_srcbuf[g_start[c] + pos] = r;
        }
    }
}

// ---- convert W [1024x128] fp32 -> fp16 ----
__global__ void wh_kernel(const float* __restrict__ W) {
    int idx = blockIdx.x * blockDim.x + threadIdx.x;
    if (idx < INC * HIDD) g_wh[idx] = __float2half_rn(W[idx]);
}

// ==== GEMM via WMMA fp16 (m16n16k16): A converted in-kernel, B via cp.async ====
// BM=128, BN=128, BK=32, 256 threads (8 warps: 2x4, each warp 64x32).
// Two-barrier pipeline skeleton (R9/R14-proven): the END-of-iteration barrier is
// what makes prefetch-into-the-other-buffer at the TOP of the next iteration safe.
#define LDA_H 40    // 32 + 8 pad (halves); row stride 80B -- multiple of 16B
#define LDB_H 136   // 128 + 8 pad (halves); row stride 272B -- multiple of 16B
#define ASZH (128 * LDA_H)   // 5120 halves = 10240 B per stage
#define BSZH (32 * LDB_H)    // 4352 halves =  8704 B per stage
#define NC   (INC / 32)      // 32 K-chunks
#define LDS  132             // epilogue staging stride (floats)
#define GEMM_SMEM (128 * LDS * 4)   // 67584 B (epilogue dominates; pipeline fits inside)

__device__ __forceinline__ uint32_t smem_u32(const void* p) {
    uint32_t a;
    asm("{ .reg .u64 t; cvta.to.shared.u64 t, %1; cvt.u32.u64 %0, t; }"
        : "=r"(a) : "l"(p));
    return a;
}
__device__ __forceinline__ void cp_async16(uint32_t dst, const void* src) {
    asm volatile("cp.async.cg.shared.global [%0], [%1], 16;"
                 :: "r"(dst), "l"(src));
}
#define CP_COMMIT() asm volatile("cp.async.commit_group;" ::: "memory")
#define CP_WAIT(N)  asm volatile("cp.async.wait_group %0;" :: "n"(N) : "memory")

__global__ __launch_bounds__(256, 2)
void gemm_wmma_kernel(const float* __restrict__ X) {
    extern __shared__ __align__(16) char smem[];
    __half* sAh[2] = { (__half*)smem, (__half*)smem + ASZH };
    __half* sBh[2] = { (__half*)smem + 2 * ASZH, (__half*)smem + 2 * ASZH + BSZH };

    const int tid = threadIdx.x;
    const int wid = tid >> 5;
    const int wr = wid >> 2;          // 0..1  (64-row band)
    const int wc = wid & 3;           // 0..3  (32-col band)
    const int bm = blockIdx.x * 128;

    // A staging coords: thread covers rows arow+i*32 (i<4), cols ac4..ac4+3
    const int arow = tid >> 3,  ac4 = (tid & 7) * 4;
    // B staging coords: thread covers rows brow, brow+16; 16B at bcol8
    const int brow = tid >> 4,  bcol8 = (tid & 15) * 8;
    uint32_t aBbase[2] = { smem_u32(sBh[0]), smem_u32(sBh[1]) };

    const float* aSrc[4];
    bool okA[4];
    #pragma unroll
    for (int i = 0; i < 4; i++) {
        int row = arow + i * 32;
        aSrc[i] = X + (size_t)(bm + row) * INC + ac4;
        okA[i]  = (bm + row < NN);
    }
    const __half* bSrc[2];
    #pragma unroll
    for (int i = 0; i < 2; i++)
        bSrc[i] = g_wh + (size_t)(brow + i * 16) * HIDD + bcol8;

    wmma::fragment<wmma::accumulator, 16, 16, 16, float> acc[4][2];
    #pragma unroll
    for (int i = 0; i < 4; i++)
        #pragma unroll
        for (int j = 0; j < 2; j++)
            wmma::fill_fragment(acc[i][j], 0.0f);

    float4 rA[4];   // register staging for chunk c+1 of A

    auto ldgA = [&](int k0) {
        #pragma unroll
        for (int i = 0; i < 4; i++)
            rA[i] = okA[i] ? *(const float4*)(aSrc[i] + k0)
                           : make_float4(0.f, 0.f, 0.f, 0.f);
    };
    auto stsA = [&](int st) {
        #pragma unroll
        for (int i = 0; i < 4; i++) {
            __half2 h0 = __floats2half2_rn(rA[i].x, rA[i].y);
            __half2 h1 = __floats2half2_rn(rA[i].z, rA[i].w);
            uint2 p = make_uint2(*(uint32_t*)&h0, *(uint32_t*)&h1);
            *(uint2*)&sAh[st][(arow + i * 32) * LDA_H + ac4] = p;
        }
    };
    auto cpB = [&](int st, int k0) {
        #pragma unroll
        for (int i = 0; i < 2; i++)
            cp_async16(aBbase[st] + (uint32_t)((brow + i * 16) * LDB_H + bcol8) * 2,
                       bSrc[i] + (size_t)k0 * HIDD);
    };

    // preamble: A(0) staged, B(0) in flight
    ldgA(0);
    stsA(0);
    cpB(0, 0);
    CP_COMMIT();
    __syncthreads();   // stsA(0) visible before MMA(0); pairs with loop structure

    for (int c = 0; c < NC; c++) {
        int st = c & 1;
        if (c + 1 < NC) {
            ldgA((c + 1) * 32);            // regs; consumed at stsA after MMA
            // safe: end-of-iteration barrier of (c-1) guarantees all warps
            // finished MMA(c-1) reads of buffer st^1 before these writes.
            cpB(st ^ 1, (c + 1) * 32);
            CP_COMMIT();
            CP_WAIT(1);                    // B(c) resident
        } else {
            CP_WAIT(0);
        }
        __syncthreads();                   // B(c) visible; A(c) already visible

        const __half* cA = sAh[st];
        const __half* cB = sBh[st];
        #pragma unroll
        for (int ks = 0; ks < 2; ks++) {
            wmma::fragment<wmma::matrix_a, 16, 16, 16, __half, wmma::row_major> af[4];
            wmma::fragment<wmma::matrix_b, 16, 16, 16, __half, wmma::row_major> bf[2];
            #pragma unroll
            for (int i = 0; i < 4; i++)
                wmma::load_matrix_sync(af[i],
                    cA + (wr * 64 + i * 16) * LDA_H + ks * 16, LDA_H);
            #pragma unroll
            for (int j = 0; j < 2; j++)
                wmma::load_matrix_sync(bf[j],
                    cB + (ks * 16) * LDB_H + wc * 32 + j * 16, LDB_H);
            #pragma unroll
            for (int i = 0; i < 4; i++)
                #pragma unroll
                for (int j = 0; j < 2; j++)
                    wmma::mma_sync(acc[i][j], af[i], bf[j], acc[i][j]);
        }

        if (c + 1 < NC)
            stsA(st ^ 1);   // after first barrier: all MMA(c-1) reads of st^1 done

        __syncthreads();    // END barrier: protects next iteration's cpB(st)
                            // and makes stsA(st^1) visible for MMA(c+1)
    }

    // ---- epilogue: stage fp32 -> scale by dinv[row] -> half2 -> g_hsb ----
    float* stage = (float*)smem;           // pipeline smem dead; reuse as staging
    #pragma unroll
    for (int i = 0; i < 4; i++)
        #pragma unroll
        for (int j = 0; j < 2; j++)
            wmma::store_matrix_sync(stage + (wr * 64 + i * 16) * LDS + wc * 32 + j * 16,
                                    acc[i][j], LDS, wmma::mem_row_major);
    __syncthreads();

    #pragma unroll
    for (int p = 0; p < 32; p++) {
        int idx  = tid + p * 256;        // 0..8191
        int row  = idx >> 6;             // 0..127
        int col2 = idx & 63;             // half2 index in row
        int grow = bm + row;
        float dv = (grow < NN) ? g_dinv[grow] : 0.0f;
        float2 v;
        v.x = stage[row * LDS + col2 * 2 + 0] * dv;
        v.y = stage[row * LDS + col2 * 2 + 1] * dv;
        __half2 h = __float22half2_rn(v);
        ((__half2*)g_hsb)[(size_t)grow * 64 + col2] = h;
    }
}

// -------- gather-reduce: one warp per destination node, 2-edge unroll --------
// hs rows carry h*dinv already:  out[d] = dinv[d] * ( sum_src hs[src] + hs[d] )
__global__ void gather_kernel(float* __restrict__ out) {
    int gw = (blockIdx.x * blockDim.x + threadIdx.x) >> 5;
    int lane = threadIdx.x & 31;
    if (gw >= NN) return;
    const uint2* hsb = (const uint2*)g_hsb;   // 32 uint2/row; lane -> cols [4*lane,4*lane+4)
    int s0 = g_start[gw], s1 = g_start[gw + 1];
    float dself = g_dinv[gw];

    auto cvt = [](uint2 r) {
        __half2 a = *(__half2*)&r.x;
        __half2 b = *(__half2*)&r.y;
        float2 fa = __half22float2(a);
        float2 fb = __half22float2(b);
        return make_float4(fa.x, fa.y, fb.x, fb.y);
    };

    float4 acc0 = cvt(__ldg(&hsb[(size_t)gw * 32 + lane]));   // self-loop term
    float4 acc1 = make_float4(0.f, 0.f, 0.f, 0.f);
    int j = s0;
    for (; j + 1 < s1; j += 2) {
        int src0 = __ldg(&g_srcbuf[j]);
        int src1 = __ldg(&g_srcbuf[j + 1]);
        float4 v0 = cvt(__ldg(&hsb[(size_t)src0 * 32 + lane]));
        float4 v1 = cvt(__ldg(&hsb[(size_t)src1 * 32 + lane]));
        acc0.x += v0.x; acc0.y += v0.y; acc0.z += v0.z; acc0.w += v0.w;
        acc1.x += v1.x; acc1.y += v1.y; acc1.z += v1.z; acc1.w += v1.w;
    }
    if (j < s1) {
        int src = __ldg(&g_srcbuf[j]);
        float4 v = cvt(__ldg(&hsb[(size_t)src * 32 + lane]));
        acc0.x += v.x; acc0.y += v.y; acc0.z += v.z; acc0.w += v.w;
    }
    float4 r;
    r.x = (acc0.x + acc1.x) * dself;
    r.y = (acc0.y + acc1.y) * dself;
    r.z = (acc0.z + acc1.z) * dself;
    r.w = (acc0.w + acc1.w) * dself;
    ((float4*)out)[(size_t)gw * 32 + lane] = r;
}

extern "C" void kernel_launch(void* const* d_in, const int* in_sizes, int n_in,
                              void* d_out, int out_size) {
    const float* X  = (const float*)d_in[0];
    const float* W  = (const float*)d_in[1];
    const int*   ei = (const int*)d_in[2];
    float* out = (float*)d_out;

    cudaFuncSetAttribute(gemm_wmma_kernel,
                         cudaFuncAttributeMaxDynamicSharedMemorySize, GEMM_SMEM);

    init_kernel     <<<(NN + 255) / 256, 256>>>();
    count_kernel    <<<(NE + 255) / 256, 256>>>(ei);
    blocksum_kernel <<<NB, 1024>>>();
    bscan_kernel    <<<1, 128>>>();
    bapply_kernel   <<<NB, 1024>>>();
    fill_kernel     <<<(NE + 255) / 256, 256>>>(ei);
    wh_kernel       <<<(INC * HIDD + 255) / 256, 256>>>(W);
    gemm_wmma_kernel<<<(NN + 127) / 128, 256, GEMM_SMEM>>>(X);
    gather_kernel   <<<(NN * 32 + 255) / 256, 256>>>(out);
}